// round 2
// baseline (speedup 1.0000x reference)
#include <cuda_runtime.h>
#include <cstdint>

#define Bn   4
#define Ln   8
#define Nn   2048
#define Cn   32
#define MIDn 64
#define OUTn 128
#define Mn   1024
#define KSn  32
#define KMn  192
#define BLn  32

__device__ float g_ft[BLn * Nn * Cn];
__device__ float g_x[Bn * Ln * KMn * Mn];
__device__ float g_W2[MIDn * 96];
__device__ float g_mean[Ln * KMn];
__device__ float g_rstd[Ln * KMn];

// ---------------------------------------------------------------------------
// 1) Transpose features (B,L,C,N) -> g_ft[frame][n][c]; block(0,0) also builds W2
// ---------------------------------------------------------------------------
__global__ void transpose_feat_kernel(const float* __restrict__ feat,
                                      const float* __restrict__ cdw,
                                      const float* __restrict__ cfw) {
    __shared__ float sm[32][33];
    int f  = blockIdx.y;
    int n0 = blockIdx.x * 32;
    int tx = threadIdx.x, ty = threadIdx.y;
    sm[ty][tx] = feat[((size_t)f * Cn + ty) * Nn + n0 + tx];
    if (blockIdx.x == 0 && blockIdx.y == 0) {
        int tid = ty * 32 + tx;
        for (int idx = tid; idx < MIDn * 96; idx += 1024) {
            int oo = idx / 96, r = idx % 96, c = r / 3, d = r % 3;
            g_W2[idx] = cfw[oo * Cn + c] * cdw[oo * 3 + d];
        }
    }
    __syncthreads();
    g_ft[((size_t)f * Nn + n0 + ty) * Cn + tx] = sm[tx][ty];
}

// ---------------------------------------------------------------------------
// 2) FPS: 32 blocks x 256 threads, 8 points/thread in registers.
//    Reduction: redux.sync (warp) + atomicMax u64 packed (block).
//    Pack = (valbits << 32) | (~index)  -> max value, ties -> lowest index.
// ---------------------------------------------------------------------------
__global__ void __launch_bounds__(256)
fps_kernel(const float* __restrict__ xyz, float* __restrict__ dout) {
    __shared__ float4 pts[Nn];
    __shared__ unsigned long long pk[2];

    int f = blockIdx.x;
    int tid = threadIdx.x, lane = tid & 31;

    const float* base = xyz + (size_t)f * Nn * 3;
    for (int p = tid; p < Nn; p += 256)
        pts[p] = make_float4(base[3*p], base[3*p+1], base[3*p+2], 0.f);
    if (tid < 2) pk[tid] = 0ull;
    __syncthreads();

    float px[8], py[8], pz[8], md[8];
#pragma unroll
    for (int j = 0; j < 8; ++j) {
        float4 q = pts[tid + j * 256];
        px[j] = q.x; py[j] = q.y; pz[j] = q.z;
        md[j] = 3.4028234663852886e38f;
    }

    float4 sp = pts[0];
    for (int i = 0; i < Mn; ++i) {
        if (tid == 0) {
            float* o = dout + ((size_t)f * Mn + i) * 3;
            o[0] = sp.x; o[1] = sp.y; o[2] = sp.z;
        }
        float bv = -1.f; int bi = 0x7fffffff;
#pragma unroll
        for (int j = 0; j < 8; ++j) {
            float dx = px[j] - sp.x, dy = py[j] - sp.y, dz = pz[j] - sp.z;
            float d  = fmaf(dx, dx, fmaf(dy, dy, dz * dz));
            float nm = fminf(md[j], d);
            md[j] = nm;
            if (nm > bv) { bv = nm; bi = tid + j * 256; }  // strict > keeps lowest idx
        }
        // distances >= 0 so float bit pattern is order-preserving as u32
        unsigned vb   = __float_as_uint(bv);
        unsigned wmax = __reduce_max_sync(0xffffffffu, vb);
        unsigned cidx = (vb == wmax) ? (unsigned)bi : 0xffffffffu;
        unsigned widx = __reduce_min_sync(0xffffffffu, cidx);

        int s = i & 1;
        if (lane == 0)
            atomicMax(&pk[s], ((unsigned long long)wmax << 32) |
                              (unsigned long long)(0xffffffffu - widx));
        __syncthreads();
        unsigned long long p64 = pk[s];
        int idx = (int)(0xffffffffu - (unsigned)(p64 & 0xffffffffu));
        sp = pts[idx];
        if (tid == 0) pk[s ^ 1] = 0ull;   // buffer for iter i+1; guarded by barrier below
        __syncthreads();
    }
}

// ---------------------------------------------------------------------------
// 3) Ball query + grouped conv via moment S, fused small GEMM.
//    512 threads: 16 warps x 4 anchors each. grid (16 tiles, 3 offsets, 32 frames)
// ---------------------------------------------------------------------------
__global__ void __launch_bounds__(512)
group_conv_kernel(const float* __restrict__ xyz,
                  const float* __restrict__ anchors)
{
    extern __shared__ char smraw[];
    float4* npts = (float4*)smraw;                        // 32768 B
    float*  Ssm  = (float*)(smraw + 32768);               // 64*96*4 = 24576
    float*  W2   = (float*)(smraw + 32768 + 24576);       // 24576
    int*    cand = (int*)  (smraw + 32768 + 49152);       // 16 warps * 32 * 4 = 2048

    int tile = blockIdx.x;
    int o    = blockIdx.y;
    int f    = blockIdx.z;
    int b = f >> 3, l = f & 7;
    int tid = threadIdx.x, lane = tid & 31, wid = tid >> 5;

    int ln = l + o - 1;
    if (ln < 0 || ln >= Ln) {
        for (int idx = tid; idx < 4096; idx += 512) {
            int kk = idx >> 6, mm = idx & 63;
            g_x[((size_t)f * KMn + o * MIDn + kk) * Mn + tile * 64 + mm] = 0.f;
        }
        return;
    }
    int nbr = b * Ln + ln;

    const float* nb = xyz + (size_t)nbr * Nn * 3;
    for (int p = tid; p < Nn; p += 512)
        npts[p] = make_float4(nb[3*p], nb[3*p+1], nb[3*p+2], 0.f);
    for (int idx = tid; idx < MIDn * 96; idx += 512)
        W2[idx] = g_W2[idx];
    __syncthreads();

    int* candw = cand + wid * 32;
    const float* fb = g_ft + (size_t)nbr * Nn * Cn;

    for (int aa = 0; aa < 4; ++aa) {
        int a_local = wid * 4 + aa;
        int a = tile * 64 + a_local;
        const float* ap = anchors + ((size_t)f * Mn + a) * 3;
        float ax = ap[0], ay = ap[1], az = ap[2];

        // ball query: first 32 indices (ascending) with d2 < 0.04
        int cnt = 0;
        for (int basej = 0; basej < Nn && cnt < KSn; basej += 32) {
            int j = basej + lane;
            float4 p = npts[j];
            float dx = p.x - ax, dy = p.y - ay, dz = p.z - az;
            float d2 = fmaf(dx, dx, fmaf(dy, dy, dz * dz));
            bool in = d2 < 0.04f;
            unsigned msk = __ballot_sync(0xffffffffu, in);
            if (in) {
                int pos = cnt + __popc(msk & ((1u << lane) - 1u));
                if (pos < KSn) candw[pos] = j;
            }
            cnt += __popc(msk);
        }
        __syncwarp();
        int cc = cnt < KSn ? cnt : KSn;
        int fill0 = (cc > 0) ? candw[0] : 0;
        __syncwarp();
        if (lane >= cc) candw[lane] = fill0;
        __syncwarp();

        // moment S[c,d] = sum_k f[k,c] * disp[k,d], lane = channel c
        float a0 = 0.f, a1 = 0.f, a2 = 0.f;
#pragma unroll 8
        for (int k = 0; k < KSn; ++k) {
            int j = candw[k];
            float4 p = npts[j];
            float fv = fb[(size_t)j * Cn + lane];
            a0 = fmaf(fv, p.x - ax, a0);
            a1 = fmaf(fv, p.y - ay, a1);
            a2 = fmaf(fv, p.z - az, a2);
        }
        Ssm[a_local * 96 + lane * 3 + 0] = a0;
        Ssm[a_local * 96 + lane * 3 + 1] = a1;
        Ssm[a_local * 96 + lane * 3 + 2] = a2;
    }
    __syncthreads();

    // GEMM: out[64 o][64 a] = W2[64][96] @ S^T ; 512 thr -> 4x2 per thread
    int o0 = (tid & 15) * 4;
    int aq = (tid >> 4) * 2;
    float acc[4][2] = {};
    for (int i = 0; i < 96; i += 4) {
        float4 w[4], s[2];
#pragma unroll
        for (int q = 0; q < 4; ++q) w[q] = *(const float4*)&W2[(o0 + q) * 96 + i];
#pragma unroll
        for (int r = 0; r < 2; ++r) s[r] = *(const float4*)&Ssm[(aq + r) * 96 + i];
#pragma unroll
        for (int q = 0; q < 4; ++q)
#pragma unroll
            for (int r = 0; r < 2; ++r)
                acc[q][r] += w[q].x * s[r].x + w[q].y * s[r].y
                           + w[q].z * s[r].z + w[q].w * s[r].w;
    }
#pragma unroll
    for (int q = 0; q < 4; ++q)
#pragma unroll
        for (int r = 0; r < 2; ++r)
            g_x[((size_t)f * KMn + o * MIDn + o0 + q) * Mn + tile * 64 + aq + r] = acc[q][r];
}

// ---------------------------------------------------------------------------
// 4) BN stats per (l, km) over 4096 values, float4 vectorized (MLP 8)
// ---------------------------------------------------------------------------
__global__ void stats_kernel() {
    int pair = blockIdx.x;
    int l = pair / KMn, km = pair % KMn;
    int tid = threadIdx.x;
    float s1 = 0.f, s2 = 0.f;
#pragma unroll
    for (int b = 0; b < Bn; ++b) {
        const float4* row = (const float4*)(g_x + ((size_t)((b * Ln + l) * KMn + km)) * Mn);
#pragma unroll
        for (int m = 0; m < 2; ++m) {
            float4 v = row[tid + m * 128];
            s1 += v.x + v.y + v.z + v.w;
            s2 += v.x*v.x + v.y*v.y + v.z*v.z + v.w*v.w;
        }
    }
    __shared__ float sh1[4], sh2[4];
#pragma unroll
    for (int off = 16; off > 0; off >>= 1) {
        s1 += __shfl_down_sync(0xffffffffu, s1, off);
        s2 += __shfl_down_sync(0xffffffffu, s2, off);
    }
    int lane = tid & 31, w = tid >> 5;
    if (lane == 0) { sh1[w] = s1; sh2[w] = s2; }
    __syncthreads();
    if (tid == 0) {
        float t1 = sh1[0] + sh1[1] + sh1[2] + sh1[3];
        float t2 = sh2[0] + sh2[1] + sh2[2] + sh2[3];
        float mean = t1 * (1.f / 4096.f);
        float var  = t2 * (1.f / 4096.f) - mean * mean;
        g_mean[pair] = mean;
        g_rstd[pair] = rsqrtf(var + 1e-5f);
    }
}

// ---------------------------------------------------------------------------
// 5) Fused BN + ReLU + temporal GEMM
// ---------------------------------------------------------------------------
__global__ void __launch_bounds__(256)
bn_gemm_kernel(const float* __restrict__ gamma, const float* __restrict__ beta,
               const float* __restrict__ tw, float* __restrict__ dout)
{
    extern __shared__ float smf[];
    float* xsm  = smf;           // [192][128]
    float* twsm = smf + 24576;   // [128][192]

    int f = blockIdx.y, l = f & 7;
    int mb = blockIdx.x * 128;
    int tid = threadIdx.x;

    for (int idx = tid; idx < KMn * 128; idx += 256) {
        int k = idx >> 7, m = idx & 127;
        float v  = g_x[((size_t)f * KMn + k) * Mn + mb + m];
        float xn = (v - g_mean[l * KMn + k]) * g_rstd[l * KMn + k] * gamma[k] + beta[k];
        xsm[idx] = fmaxf(xn, 0.f);
    }
    for (int idx = tid; idx < OUTn * KMn; idx += 256) twsm[idx] = tw[idx];
    __syncthreads();

    int o0 = (tid >> 4) * 8;
    int m0 = (tid & 15) * 8;
    float acc[8][8] = {};
    for (int k = 0; k < KMn; k += 4) {
        float4 wv[8];
#pragma unroll
        for (int q = 0; q < 8; ++q) wv[q] = *(const float4*)&twsm[(o0 + q) * KMn + k];
        float4 xa[4], xb[4];
#pragma unroll
        for (int j = 0; j < 4; ++j) {
            xa[j] = *(const float4*)&xsm[(k + j) * 128 + m0];
            xb[j] = *(const float4*)&xsm[(k + j) * 128 + m0 + 4];
        }
#pragma unroll
        for (int q = 0; q < 8; ++q) {
            const float* wq = (const float*)&wv[q];
#pragma unroll
            for (int j = 0; j < 4; ++j) {
                float w = wq[j];
                const float* pa = (const float*)&xa[j];
                const float* pb = (const float*)&xb[j];
#pragma unroll
                for (int r = 0; r < 4; ++r) {
                    acc[q][r]     += w * pa[r];
                    acc[q][4 + r] += w * pb[r];
                }
            }
        }
    }
    float* outb = dout + (size_t)BLn * Mn * 3 + ((size_t)f * OUTn) * Mn + mb;
#pragma unroll
    for (int q = 0; q < 8; ++q)
#pragma unroll
        for (int r = 0; r < 8; ++r)
            outb[(size_t)(o0 + q) * Mn + m0 + r] = acc[q][r];
}

// ---------------------------------------------------------------------------
extern "C" void kernel_launch(void* const* d_in, const int* in_sizes, int n_in,
                              void* d_out, int out_size) {
    const float* xyzs     = (const float*)d_in[0];
    const float* features = (const float*)d_in[1];
    const float* cdw      = (const float*)d_in[2];
    const float* cfw      = (const float*)d_in[3];
    const float* gamma    = (const float*)d_in[4];
    const float* beta     = (const float*)d_in[5];
    const float* tw       = (const float*)d_in[6];
    float* out = (float*)d_out;

    cudaFuncSetAttribute(group_conv_kernel, cudaFuncAttributeMaxDynamicSharedMemorySize, 84000);
    cudaFuncSetAttribute(bn_gemm_kernel,    cudaFuncAttributeMaxDynamicSharedMemorySize, 196608);

    transpose_feat_kernel<<<dim3(64, 32), dim3(32, 32)>>>(features, cdw, cfw);
    fps_kernel<<<32, 256>>>(xyzs, out);
    group_conv_kernel<<<dim3(16, 3, 32), 512, 84000>>>(xyzs, out);
    stats_kernel<<<Ln * KMn, 128>>>();
    bn_gemm_kernel<<<dim3(8, 32), 256, 196608>>>(gamma, beta, tw, out);
}

// round 3
// speedup vs baseline: 1.1443x; 1.1443x over previous
#include <cuda_runtime.h>
#include <cstdint>

#define Bn   4
#define Ln   8
#define Nn   2048
#define Cn   32
#define MIDn 64
#define OUTn 128
#define Mn   1024
#define KSn  32
#define KMn  192
#define BLn  32
#define FLTMAXC 3.4028234663852886e38f

__device__ float g_ft[BLn * Nn * Cn];
__device__ float g_x[Bn * Ln * KMn * Mn];
__device__ float g_W2[MIDn * 96];
__device__ float g_mean[Ln * KMn];
__device__ float g_rstd[Ln * KMn];

// ---------------------------------------------------------------------------
// 1) Transpose features (B,L,C,N) -> g_ft[frame][n][c]; block(0,0) also builds W2
// ---------------------------------------------------------------------------
__global__ void transpose_feat_kernel(const float* __restrict__ feat,
                                      const float* __restrict__ cdw,
                                      const float* __restrict__ cfw) {
    __shared__ float sm[32][33];
    int f  = blockIdx.y;
    int n0 = blockIdx.x * 32;
    int tx = threadIdx.x, ty = threadIdx.y;
    sm[ty][tx] = feat[((size_t)f * Cn + ty) * Nn + n0 + tx];
    if (blockIdx.x == 0 && blockIdx.y == 0) {
        int tid = ty * 32 + tx;
        for (int idx = tid; idx < MIDn * 96; idx += 1024) {
            int oo = idx / 96, r = idx % 96, c = r / 3, d = r % 3;
            g_W2[idx] = cfw[oo * Cn + c] * cdw[oo * 3 + d];
        }
    }
    __syncthreads();
    g_ft[((size_t)f * Nn + n0 + ty) * Cn + tx] = sm[tx][ty];
}

// ---------------------------------------------------------------------------
// 2) FPS: 32 blocks x 128 threads (4 warps), 16 points/thread in registers.
//    Per iter: warp redux (max val, min idx) -> leader packs u64 into a
//    parity double-buffered smem slot -> ONE __syncthreads -> every warp
//    redundantly reduces the 4 packed words. No atomics, one barrier/iter.
//    Pack = (valbits << 32) | ~idx  => u64 max == (max val, min idx).
// ---------------------------------------------------------------------------
__global__ void __launch_bounds__(128)
fps_kernel(const float* __restrict__ xyz, float* __restrict__ dout) {
    __shared__ float4 pts[Nn];                  // 32 KB
    __shared__ float  anch[Mn * 3];             // 12 KB
    __shared__ unsigned long long pk[2][4];

    int f = blockIdx.x;
    int tid = threadIdx.x, lane = tid & 31, wid = tid >> 5;

    const float* base = xyz + (size_t)f * Nn * 3;
    for (int p = tid; p < Nn; p += 128)
        pts[p] = make_float4(base[3*p], base[3*p+1], base[3*p+2], 0.f);
    __syncthreads();

    float px[16], py[16], pz[16], md[16];
#pragma unroll
    for (int j = 0; j < 16; ++j) {
        float4 q = pts[tid + j * 128];
        px[j] = q.x; py[j] = q.y; pz[j] = q.z;
        md[j] = FLTMAXC;
    }
    float sx = pts[0].x, sy = pts[0].y, sz = pts[0].z;

    for (int i = 0; i < Mn; ++i) {
        if (tid == 0) { anch[3*i] = sx; anch[3*i+1] = sy; anch[3*i+2] = sz; }

        float bv = -1.f; unsigned bi = 0xffffffffu;
#pragma unroll
        for (int j = 0; j < 16; ++j) {
            float dx = px[j] - sx, dy = py[j] - sy, dz = pz[j] - sz;
            float d  = fmaf(dx, dx, fmaf(dy, dy, dz * dz));
            float nm = fminf(md[j], d);
            md[j] = nm;
            // strict > keeps lowest index within thread (idx ascends with j)
            if (nm > bv) { bv = nm; bi = (unsigned)(tid + j * 128); }
        }
        // distances >= 0: float bits order-preserving as u32
        unsigned vb   = __float_as_uint(bv);
        unsigned wmax = __reduce_max_sync(0xffffffffu, vb);
        unsigned cidx = (vb == wmax) ? bi : 0xffffffffu;
        unsigned widx = __reduce_min_sync(0xffffffffu, cidx);

        int s = i & 1;
        if (lane == 0)
            pk[s][wid] = ((unsigned long long)wmax << 32) |
                         (unsigned long long)(~widx);
        __syncthreads();

        unsigned long long m0 = pk[s][0], m1 = pk[s][1];
        unsigned long long m2 = pk[s][2], m3 = pk[s][3];
        unsigned long long ma = (m0 > m1) ? m0 : m1;
        unsigned long long mb = (m2 > m3) ? m2 : m3;
        unsigned long long mm = (ma > mb) ? ma : mb;
        int idx = (int)(~(unsigned)mm);
        float4 spv = pts[idx];
        sx = spv.x; sy = spv.y; sz = spv.z;
    }
    __syncthreads();
    float* o = dout + (size_t)f * Mn * 3;
    const float4* a4 = (const float4*)anch;
    for (int p = tid; p < (Mn * 3) / 4; p += 128)
        ((float4*)o)[p] = a4[p];
}

// ---------------------------------------------------------------------------
// 3) Ball query + grouped conv via moment S, fused small GEMM.
//    512 threads: 16 warps x 4 anchors each. grid (16 tiles, 3 offsets, 32 frames)
// ---------------------------------------------------------------------------
__global__ void __launch_bounds__(512)
group_conv_kernel(const float* __restrict__ xyz,
                  const float* __restrict__ anchors)
{
    extern __shared__ char smraw[];
    float4* npts = (float4*)smraw;                        // 32768 B
    float*  Ssm  = (float*)(smraw + 32768);               // 24576
    float*  W2   = (float*)(smraw + 32768 + 24576);       // 24576
    int*    cand = (int*)  (smraw + 32768 + 49152);       // 2048

    int tile = blockIdx.x;
    int o    = blockIdx.y;
    int f    = blockIdx.z;
    int b = f >> 3, l = f & 7;
    int tid = threadIdx.x, lane = tid & 31, wid = tid >> 5;

    int ln = l + o - 1;
    if (ln < 0 || ln >= Ln) {
        for (int idx = tid; idx < 4096; idx += 512) {
            int kk = idx >> 6, mm = idx & 63;
            g_x[((size_t)f * KMn + o * MIDn + kk) * Mn + tile * 64 + mm] = 0.f;
        }
        return;
    }
    int nbr = b * Ln + ln;

    const float* nb = xyz + (size_t)nbr * Nn * 3;
    for (int p = tid; p < Nn; p += 512)
        npts[p] = make_float4(nb[3*p], nb[3*p+1], nb[3*p+2], 0.f);
    for (int idx = tid; idx < MIDn * 96; idx += 512)
        W2[idx] = g_W2[idx];
    __syncthreads();

    int* candw = cand + wid * 32;
    const float* fb = g_ft + (size_t)nbr * Nn * Cn;

    for (int aa = 0; aa < 4; ++aa) {
        int a_local = wid * 4 + aa;
        int a = tile * 64 + a_local;
        const float* ap = anchors + ((size_t)f * Mn + a) * 3;
        float ax = ap[0], ay = ap[1], az = ap[2];

        int cnt = 0;
        for (int basej = 0; basej < Nn && cnt < KSn; basej += 32) {
            int j = basej + lane;
            float4 p = npts[j];
            float dx = p.x - ax, dy = p.y - ay, dz = p.z - az;
            float d2 = fmaf(dx, dx, fmaf(dy, dy, dz * dz));
            bool in = d2 < 0.04f;
            unsigned msk = __ballot_sync(0xffffffffu, in);
            if (in) {
                int pos = cnt + __popc(msk & ((1u << lane) - 1u));
                if (pos < KSn) candw[pos] = j;
            }
            cnt += __popc(msk);
        }
        __syncwarp();
        int cc = cnt < KSn ? cnt : KSn;
        int fill0 = (cc > 0) ? candw[0] : 0;
        __syncwarp();
        if (lane >= cc) candw[lane] = fill0;
        __syncwarp();

        float a0 = 0.f, a1 = 0.f, a2 = 0.f;
#pragma unroll 8
        for (int k = 0; k < KSn; ++k) {
            int j = candw[k];
            float4 p = npts[j];
            float fv = fb[(size_t)j * Cn + lane];
            a0 = fmaf(fv, p.x - ax, a0);
            a1 = fmaf(fv, p.y - ay, a1);
            a2 = fmaf(fv, p.z - az, a2);
        }
        Ssm[a_local * 96 + lane * 3 + 0] = a0;
        Ssm[a_local * 96 + lane * 3 + 1] = a1;
        Ssm[a_local * 96 + lane * 3 + 2] = a2;
    }
    __syncthreads();

    int o0 = (tid & 15) * 4;
    int aq = (tid >> 4) * 2;
    float acc[4][2] = {};
    for (int i = 0; i < 96; i += 4) {
        float4 w[4], s[2];
#pragma unroll
        for (int q = 0; q < 4; ++q) w[q] = *(const float4*)&W2[(o0 + q) * 96 + i];
#pragma unroll
        for (int r = 0; r < 2; ++r) s[r] = *(const float4*)&Ssm[(aq + r) * 96 + i];
#pragma unroll
        for (int q = 0; q < 4; ++q)
#pragma unroll
            for (int r = 0; r < 2; ++r)
                acc[q][r] += w[q].x * s[r].x + w[q].y * s[r].y
                           + w[q].z * s[r].z + w[q].w * s[r].w;
    }
#pragma unroll
    for (int q = 0; q < 4; ++q)
#pragma unroll
        for (int r = 0; r < 2; ++r)
            g_x[((size_t)f * KMn + o * MIDn + o0 + q) * Mn + tile * 64 + aq + r] = acc[q][r];
}

// ---------------------------------------------------------------------------
// 4) BN stats per (l, km) over 4096 values, float4 vectorized
// ---------------------------------------------------------------------------
__global__ void stats_kernel() {
    int pair = blockIdx.x;
    int l = pair / KMn, km = pair % KMn;
    int tid = threadIdx.x;
    float s1 = 0.f, s2 = 0.f;
#pragma unroll
    for (int b = 0; b < Bn; ++b) {
        const float4* row = (const float4*)(g_x + ((size_t)((b * Ln + l) * KMn + km)) * Mn);
#pragma unroll
        for (int m = 0; m < 2; ++m) {
            float4 v = row[tid + m * 128];
            s1 += v.x + v.y + v.z + v.w;
            s2 += v.x*v.x + v.y*v.y + v.z*v.z + v.w*v.w;
        }
    }
    __shared__ float sh1[4], sh2[4];
#pragma unroll
    for (int off = 16; off > 0; off >>= 1) {
        s1 += __shfl_down_sync(0xffffffffu, s1, off);
        s2 += __shfl_down_sync(0xffffffffu, s2, off);
    }
    int lane = tid & 31, w = tid >> 5;
    if (lane == 0) { sh1[w] = s1; sh2[w] = s2; }
    __syncthreads();
    if (tid == 0) {
        float t1 = sh1[0] + sh1[1] + sh1[2] + sh1[3];
        float t2 = sh2[0] + sh2[1] + sh2[2] + sh2[3];
        float mean = t1 * (1.f / 4096.f);
        float var  = t2 * (1.f / 4096.f) - mean * mean;
        g_mean[pair] = mean;
        g_rstd[pair] = rsqrtf(var + 1e-5f);
    }
}

// ---------------------------------------------------------------------------
// 5) Fused BN + ReLU + temporal GEMM
// ---------------------------------------------------------------------------
__global__ void __launch_bounds__(256)
bn_gemm_kernel(const float* __restrict__ gamma, const float* __restrict__ beta,
               const float* __restrict__ tw, float* __restrict__ dout)
{
    extern __shared__ float smf[];
    float* xsm  = smf;           // [192][128]
    float* twsm = smf + 24576;   // [128][192]

    int f = blockIdx.y, l = f & 7;
    int mb = blockIdx.x * 128;
    int tid = threadIdx.x;

    for (int idx = tid; idx < KMn * 128; idx += 256) {
        int k = idx >> 7, m = idx & 127;
        float v  = g_x[((size_t)f * KMn + k) * Mn + mb + m];
        float xn = (v - g_mean[l * KMn + k]) * g_rstd[l * KMn + k] * gamma[k] + beta[k];
        xsm[idx] = fmaxf(xn, 0.f);
    }
    for (int idx = tid; idx < OUTn * KMn; idx += 256) twsm[idx] = tw[idx];
    __syncthreads();

    int o0 = (tid >> 4) * 8;
    int m0 = (tid & 15) * 8;
    float acc[8][8] = {};
    for (int k = 0; k < KMn; k += 4) {
        float4 wv[8];
#pragma unroll
        for (int q = 0; q < 8; ++q) wv[q] = *(const float4*)&twsm[(o0 + q) * KMn + k];
        float4 xa[4], xb[4];
#pragma unroll
        for (int j = 0; j < 4; ++j) {
            xa[j] = *(const float4*)&xsm[(k + j) * 128 + m0];
            xb[j] = *(const float4*)&xsm[(k + j) * 128 + m0 + 4];
        }
#pragma unroll
        for (int q = 0; q < 8; ++q) {
            const float* wq = (const float*)&wv[q];
#pragma unroll
            for (int j = 0; j < 4; ++j) {
                float w = wq[j];
                const float* pa = (const float*)&xa[j];
                const float* pb = (const float*)&xb[j];
#pragma unroll
                for (int r = 0; r < 4; ++r) {
                    acc[q][r]     += w * pa[r];
                    acc[q][4 + r] += w * pb[r];
                }
            }
        }
    }
    float* outb = dout + (size_t)BLn * Mn * 3 + ((size_t)f * OUTn) * Mn + mb;
#pragma unroll
    for (int q = 0; q < 8; ++q)
#pragma unroll
        for (int r = 0; r < 8; ++r)
            outb[(size_t)(o0 + q) * Mn + m0 + r] = acc[q][r];
}

// ---------------------------------------------------------------------------
extern "C" void kernel_launch(void* const* d_in, const int* in_sizes, int n_in,
                              void* d_out, int out_size) {
    const float* xyzs     = (const float*)d_in[0];
    const float* features = (const float*)d_in[1];
    const float* cdw      = (const float*)d_in[2];
    const float* cfw      = (const float*)d_in[3];
    const float* gamma    = (const float*)d_in[4];
    const float* beta     = (const float*)d_in[5];
    const float* tw       = (const float*)d_in[6];
    float* out = (float*)d_out;

    cudaFuncSetAttribute(group_conv_kernel, cudaFuncAttributeMaxDynamicSharedMemorySize, 84000);
    cudaFuncSetAttribute(bn_gemm_kernel,    cudaFuncAttributeMaxDynamicSharedMemorySize, 196608);

    transpose_feat_kernel<<<dim3(64, 32), dim3(32, 32)>>>(features, cdw, cfw);
    fps_kernel<<<32, 128>>>(xyzs, out);
    group_conv_kernel<<<dim3(16, 3, 32), 512, 84000>>>(xyzs, out);
    stats_kernel<<<Ln * KMn, 128>>>();
    bn_gemm_kernel<<<dim3(8, 32), 256, 196608>>>(gamma, beta, tw, out);
}